// round 1
// baseline (speedup 1.0000x reference)
#include <cuda_runtime.h>
#include <math_constants.h>

#define TILE  2048
#define BLOCK 256

__global__ void zero_kernel(float* out) {
    if (threadIdx.x == 0) out[0] = 0.0f;
}

// One pass: for each point in `pts` find min squared distance to any point in
// `tgt` (same batch), accumulate mean into out[0].
// sqdist = x2 + (y2 - 2*x.y); we keep s = y2 - 2*x.y in the loop (3 FFMA),
// add x2 and clamp once at the end (min/clamp commute since max(.,0) monotone).
__global__ __launch_bounds__(BLOCK) void chamfer_min_kernel(
    const float* __restrict__ pts,   // [B, N, 3]
    const float* __restrict__ tgt,   // [B, M, 3]
    int N, int M, float inv, float* __restrict__ out)
{
    __shared__ float4 sm[TILE];

    const int b = blockIdx.y;
    const int n = blockIdx.x * BLOCK + threadIdx.x;
    const bool valid = (n < N);

    const float* p = pts + ((size_t)b * N + (valid ? n : 0)) * 3;
    const float px = p[0], py = p[1], pz = p[2];
    const float x2 = px * px + py * py + pz * pz;

    const float* tb = tgt + (size_t)b * M * 3;

    float mn0 = CUDART_INF_F, mn1 = CUDART_INF_F;
    float mn2 = CUDART_INF_F, mn3 = CUDART_INF_F;

    for (int m0 = 0; m0 < M; m0 += TILE) {
        // Cooperative tile load: pack (-2x, -2y, -2z, ||t||^2) per target.
        for (int j = threadIdx.x; j < TILE; j += BLOCK) {
            const int m = m0 + j;
            float4 t;
            if (m < M) {
                const float* q = tb + (size_t)m * 3;
                const float qx = q[0], qy = q[1], qz = q[2];
                t = make_float4(-2.0f * qx, -2.0f * qy, -2.0f * qz,
                                qx * qx + qy * qy + qz * qz);
            } else {
                t = make_float4(0.0f, 0.0f, 0.0f, CUDART_INF_F);
            }
            sm[j] = t;
        }
        __syncthreads();

        #pragma unroll 4
        for (int j = 0; j < TILE; j += 4) {
            const float4 t0 = sm[j + 0];
            const float4 t1 = sm[j + 1];
            const float4 t2 = sm[j + 2];
            const float4 t3 = sm[j + 3];
            const float s0 = fmaf(t0.z, pz, fmaf(t0.y, py, fmaf(t0.x, px, t0.w)));
            const float s1 = fmaf(t1.z, pz, fmaf(t1.y, py, fmaf(t1.x, px, t1.w)));
            const float s2 = fmaf(t2.z, pz, fmaf(t2.y, py, fmaf(t2.x, px, t2.w)));
            const float s3 = fmaf(t3.z, pz, fmaf(t3.y, py, fmaf(t3.x, px, t3.w)));
            mn0 = fminf(mn0, s0);
            mn1 = fminf(mn1, s1);
            mn2 = fminf(mn2, s2);
            mn3 = fminf(mn3, s3);
        }
        __syncthreads();
    }

    const float mn = fminf(fminf(mn0, mn1), fminf(mn2, mn3));
    float d = valid ? fmaxf(x2 + mn, 0.0f) : 0.0f;

    // Block reduction: warp shuffle, then cross-warp via smem.
    #pragma unroll
    for (int o = 16; o > 0; o >>= 1)
        d += __shfl_down_sync(0xffffffffu, d, o);

    __shared__ float wsum[BLOCK / 32];
    if ((threadIdx.x & 31) == 0) wsum[threadIdx.x >> 5] = d;
    __syncthreads();

    if (threadIdx.x < BLOCK / 32) {
        float v = wsum[threadIdx.x];
        #pragma unroll
        for (int o = BLOCK / 64; o > 0; o >>= 1)
            v += __shfl_down_sync(0xffu, v, o);
        if (threadIdx.x == 0) atomicAdd(out, v * inv);
    }
}

extern "C" void kernel_launch(void* const* d_in, const int* in_sizes, int n_in,
                              void* d_out, int out_size)
{
    const float* input  = (const float*)d_in[0];   // [B, N, 3]
    const float* target = (const float*)d_in[1];   // [B, M, 3]
    float* out = (float*)d_out;

    const int B = 8, D = 3;
    const int N = in_sizes[0] / (B * D);
    const int M = in_sizes[1] / (B * D);

    zero_kernel<<<1, 32>>>(out);

    dim3 g1((N + BLOCK - 1) / BLOCK, B);
    dim3 g2((M + BLOCK - 1) / BLOCK, B);
    chamfer_min_kernel<<<g1, BLOCK>>>(input, target, N, M,
                                      1.0f / ((float)B * (float)N), out);
    chamfer_min_kernel<<<g2, BLOCK>>>(target, input, M, N,
                                      1.0f / ((float)B * (float)M), out);
}

// round 2
// speedup vs baseline: 1.1065x; 1.1065x over previous
#include <cuda_runtime.h>
#include <math_constants.h>

#define TILE  1024
#define BLOCK 256

typedef unsigned long long ull;

__global__ void zero_kernel(float* out) {
    if (threadIdx.x == 0) out[0] = 0.0f;
}

__device__ __forceinline__ ull ffma2(ull a, ull b, ull c) {
    ull d;
    asm("fma.rn.f32x2 %0, %1, %2, %3;" : "=l"(d) : "l"(a), "l"(b), "l"(c));
    return d;
}
__device__ __forceinline__ ull packrep(float x) {
    ull d; asm("mov.b64 %0, {%1, %1};" : "=l"(d) : "f"(x)); return d;
}
__device__ __forceinline__ ull packf(float a, float b) {
    ull d; asm("mov.b64 %0, {%1, %2};" : "=l"(d) : "f"(a), "f"(b)); return d;
}
__device__ __forceinline__ void unpack2(ull s, float& lo, float& hi) {
    asm("mov.b64 {%0, %1}, %2;" : "=f"(lo), "=f"(hi) : "l"(s));
}

// Fused: blockIdx.x < blocksP1 -> pass1 (input vs target), else pass2 (swapped).
// Per pair: s = w - 2*t.p  computed as 3 packed FFMA2 over 2 targets at once.
// min/clamp commute: d = max(x2 + min_m s_m, 0).
__global__ __launch_bounds__(BLOCK) void chamfer_kernel(
    const float* __restrict__ input,   // [B, N, 3]
    const float* __restrict__ target,  // [B, M, 3]
    int N, int M, int blocksP1, float inv1, float inv2,
    float* __restrict__ out)
{
    __shared__ ulonglong2 smA[TILE / 2];  // (xpair, ypair)
    __shared__ ulonglong2 smB[TILE / 2];  // (zpair, wpair)

    const int b = blockIdx.y;
    const bool p2 = ((int)blockIdx.x >= blocksP1);
    const float* pts = p2 ? target : input;
    const float* tgt = p2 ? input : target;
    const int NP = p2 ? M : N;
    const int MT = p2 ? N : M;
    const float inv = p2 ? inv2 : inv1;
    const int bx = p2 ? ((int)blockIdx.x - blocksP1) : (int)blockIdx.x;

    const int n = bx * BLOCK + threadIdx.x;
    const bool valid = (n < NP);
    const float* p = pts + ((size_t)b * NP + (valid ? n : 0)) * 3;
    const float px = p[0], py = p[1], pz = p[2];
    const float x2 = px * px + py * py + pz * pz;
    const ull pxx = packrep(px), pyy = packrep(py), pzz = packrep(pz);

    const float* tb = tgt + (size_t)b * MT * 3;

    float mn0 = CUDART_INF_F, mn1 = CUDART_INF_F;
    float mn2 = CUDART_INF_F, mn3 = CUDART_INF_F;

    for (int m0 = 0; m0 < MT; m0 += TILE) {
        // Build packed-pair tile: per pair j -> targets (m0+2j, m0+2j+1).
        for (int j = threadIdx.x; j < TILE / 2; j += BLOCK) {
            const int m = m0 + 2 * j;
            float x0 = 0.f, y0 = 0.f, z0 = 0.f, w0 = CUDART_INF_F;
            float x1 = 0.f, y1 = 0.f, z1 = 0.f, w1 = CUDART_INF_F;
            if (m < MT) {
                const float* q = tb + (size_t)m * 3;
                x0 = q[0]; y0 = q[1]; z0 = q[2];
                w0 = x0 * x0 + y0 * y0 + z0 * z0;
            }
            if (m + 1 < MT) {
                const float* q = tb + (size_t)(m + 1) * 3;
                x1 = q[0]; y1 = q[1]; z1 = q[2];
                w1 = x1 * x1 + y1 * y1 + z1 * z1;
            }
            smA[j] = make_ulonglong2(packf(-2.f * x0, -2.f * x1),
                                     packf(-2.f * y0, -2.f * y1));
            smB[j] = make_ulonglong2(packf(-2.f * z0, -2.f * z1),
                                     packf(w0, w1));
        }
        __syncthreads();

        #pragma unroll 4
        for (int j = 0; j < TILE / 2; j += 2) {
            const ulonglong2 a0 = smA[j],     c0 = smB[j];
            const ulonglong2 a1 = smA[j + 1], c1 = smB[j + 1];
            ull s0 = ffma2(a0.x, pxx, c0.y);
            s0     = ffma2(a0.y, pyy, s0);
            s0     = ffma2(c0.x, pzz, s0);
            ull s1 = ffma2(a1.x, pxx, c1.y);
            s1     = ffma2(a1.y, pyy, s1);
            s1     = ffma2(c1.x, pzz, s1);
            float l0, h0, l1, h1;
            unpack2(s0, l0, h0);
            unpack2(s1, l1, h1);
            mn0 = fminf(mn0, l0);
            mn1 = fminf(mn1, h0);
            mn2 = fminf(mn2, l1);
            mn3 = fminf(mn3, h1);
        }
        __syncthreads();
    }

    const float mn = fminf(fminf(mn0, mn1), fminf(mn2, mn3));
    float d = valid ? fmaxf(x2 + mn, 0.0f) : 0.0f;

    #pragma unroll
    for (int o = 16; o > 0; o >>= 1)
        d += __shfl_down_sync(0xffffffffu, d, o);

    __shared__ float wsum[BLOCK / 32];
    if ((threadIdx.x & 31) == 0) wsum[threadIdx.x >> 5] = d;
    __syncthreads();

    if (threadIdx.x < BLOCK / 32) {
        float v = wsum[threadIdx.x];
        #pragma unroll
        for (int o = BLOCK / 64; o > 0; o >>= 1)
            v += __shfl_down_sync(0xffu, v, o);
        if (threadIdx.x == 0) atomicAdd(out, v * inv);
    }
}

extern "C" void kernel_launch(void* const* d_in, const int* in_sizes, int n_in,
                              void* d_out, int out_size)
{
    const float* input  = (const float*)d_in[0];   // [B, N, 3]
    const float* target = (const float*)d_in[1];   // [B, M, 3]
    float* out = (float*)d_out;

    const int B = 8, D = 3;
    const int N = in_sizes[0] / (B * D);
    const int M = in_sizes[1] / (B * D);

    zero_kernel<<<1, 32>>>(out);

    const int bp1 = (N + BLOCK - 1) / BLOCK;
    const int bp2 = (M + BLOCK - 1) / BLOCK;
    dim3 grid(bp1 + bp2, B);
    chamfer_kernel<<<grid, BLOCK>>>(input, target, N, M, bp1,
                                    1.0f / ((float)B * (float)N),
                                    1.0f / ((float)B * (float)M), out);
}

// round 3
// speedup vs baseline: 1.6598x; 1.5000x over previous
#include <cuda_runtime.h>
#include <math_constants.h>

#define BLOCK  256
#define PPT    4                       // points per thread
#define PTS_PER_BLOCK (BLOCK * PPT)    // 1024
#define MSPLIT 4                       // target-dim split
#define TILE   1024                    // targets per smem tile
#define BATCH  8
#define MAXPTS 65536                   // B*(N+M) for this problem

typedef unsigned long long ull;

__device__ unsigned g_min[MAXPTS];

__device__ __forceinline__ ull ffma2(ull a, ull b, ull c) {
    ull d;
    asm("fma.rn.f32x2 %0, %1, %2, %3;" : "=l"(d) : "l"(a), "l"(b), "l"(c));
    return d;
}
__device__ __forceinline__ ull packrep(float x) {
    ull d; asm("mov.b64 %0, {%1, %1};" : "=l"(d) : "f"(x)); return d;
}
__device__ __forceinline__ ull packf(float a, float b) {
    ull d; asm("mov.b64 %0, {%1, %2};" : "=l"(d) : "f"(a), "f"(b)); return d;
}
__device__ __forceinline__ void unpack2(ull s, float& lo, float& hi) {
    asm("mov.b64 {%0, %1}, %2;" : "=f"(lo), "=f"(hi) : "l"(s));
}
// Order-preserving float <-> uint mapping (works for all finite + inf values).
__device__ __forceinline__ unsigned encf(float f) {
    unsigned b = __float_as_uint(f);
    return (b & 0x80000000u) ? ~b : (b | 0x80000000u);
}
__device__ __forceinline__ float decf(unsigned u) {
    unsigned b = (u & 0x80000000u) ? (u & 0x7FFFFFFFu) : ~u;
    return __uint_as_float(b);
}

__global__ void init_kernel(float* out, int total) {
    int i = blockIdx.x * blockDim.x + threadIdx.x;
    if (i < total) g_min[i] = 0xFF800000u;   // enc(+inf)
    if (i == 0) out[0] = 0.0f;
}

// grid: (B * groups, MSPLIT, 2).  z = pass (0: input vs target, 1: swapped).
// Each block: PTS_PER_BLOCK points x one target chunk; partial min folded with
// x2 and combined globally via atomicMin on the order-preserving encoding.
__global__ __launch_bounds__(BLOCK) void chamfer_main(
    const float* __restrict__ input,   // [B, N, 3]
    const float* __restrict__ target,  // [B, M, 3]
    int N, int M)
{
    __shared__ ulonglong2 smA[TILE / 2];  // (-2x pair, -2y pair)
    __shared__ ulonglong2 smB[TILE / 2];  // (-2z pair, ||t||^2 pair)

    const int pass = blockIdx.z;
    const float* pts = pass ? target : input;
    const float* tgt = pass ? input : target;
    const int NP = pass ? M : N;
    const int MT = pass ? N : M;
    const int idbase = pass ? (BATCH * N) : 0;

    const int groups = (NP + PTS_PER_BLOCK - 1) / PTS_PER_BLOCK;
    if ((int)blockIdx.x >= BATCH * groups) return;
    const int b = blockIdx.x / groups;
    const int g = blockIdx.x % groups;

    const int chunk = (MT + MSPLIT - 1) / MSPLIT;
    const int mstart = blockIdx.y * chunk;
    const int mend = min(mstart + chunk, MT);
    if (mstart >= MT) return;

    // Load PPT points into packed-broadcast registers.
    ull pxx[PPT], pyy[PPT], pzz[PPT];
    float x2[PPT], mn[PPT];
    int nidx[PPT];
    const float* pb = pts + (size_t)b * NP * 3;
    #pragma unroll
    for (int k = 0; k < PPT; k++) {
        const int n = g * PTS_PER_BLOCK + k * BLOCK + threadIdx.x;
        nidx[k] = n;
        float px = 0.f, py = 0.f, pz = 0.f;
        if (n < NP) { px = pb[n * 3]; py = pb[n * 3 + 1]; pz = pb[n * 3 + 2]; }
        pxx[k] = packrep(px); pyy[k] = packrep(py); pzz[k] = packrep(pz);
        x2[k] = px * px + py * py + pz * pz;
        mn[k] = CUDART_INF_F;
    }
    const float* tb = tgt + (size_t)b * MT * 3;

    for (int t0 = mstart; t0 < mend; t0 += TILE) {
        for (int j = threadIdx.x; j < TILE / 2; j += BLOCK) {
            const int m = t0 + 2 * j;
            float X0 = 0.f, Y0 = 0.f, Z0 = 0.f, W0 = CUDART_INF_F;
            float X1 = 0.f, Y1 = 0.f, Z1 = 0.f, W1 = CUDART_INF_F;
            if (m < mend) {
                const float* q = tb + (size_t)m * 3;
                X0 = q[0]; Y0 = q[1]; Z0 = q[2];
                W0 = X0 * X0 + Y0 * Y0 + Z0 * Z0;
            }
            if (m + 1 < mend) {
                const float* q = tb + (size_t)(m + 1) * 3;
                X1 = q[0]; Y1 = q[1]; Z1 = q[2];
                W1 = X1 * X1 + Y1 * Y1 + Z1 * Z1;
            }
            smA[j] = make_ulonglong2(packf(-2.f * X0, -2.f * X1),
                                     packf(-2.f * Y0, -2.f * Y1));
            smB[j] = make_ulonglong2(packf(-2.f * Z0, -2.f * Z1),
                                     packf(W0, W1));
        }
        __syncthreads();

        #pragma unroll 2
        for (int j = 0; j < TILE / 2; j++) {
            const ulonglong2 a = smA[j];
            const ulonglong2 c = smB[j];
            #pragma unroll
            for (int k = 0; k < PPT; k++) {
                ull s = ffma2(a.x, pxx[k], c.y);
                s     = ffma2(a.y, pyy[k], s);
                s     = ffma2(c.x, pzz[k], s);
                float lo, hi;
                unpack2(s, lo, hi);
                mn[k] = fminf(mn[k], fminf(lo, hi));
            }
        }
        __syncthreads();
    }

    #pragma unroll
    for (int k = 0; k < PPT; k++) {
        if (nidx[k] < NP)
            atomicMin(&g_min[idbase + b * NP + nidx[k]], encf(x2[k] + mn[k]));
    }
}

__global__ void finalize_kernel(float* __restrict__ out, int BN, int total,
                                float inv1, float inv2)
{
    const int i = blockIdx.x * blockDim.x + threadIdx.x;
    float v = 0.0f;
    if (i < total) {
        const float d = fmaxf(decf(g_min[i]), 0.0f);
        v = d * ((i < BN) ? inv1 : inv2);
    }
    #pragma unroll
    for (int o = 16; o > 0; o >>= 1)
        v += __shfl_down_sync(0xffffffffu, v, o);

    __shared__ float wsum[BLOCK / 32];
    if ((threadIdx.x & 31) == 0) wsum[threadIdx.x >> 5] = v;
    __syncthreads();
    if (threadIdx.x < BLOCK / 32) {
        float s = wsum[threadIdx.x];
        #pragma unroll
        for (int o = BLOCK / 64; o > 0; o >>= 1)
            s += __shfl_down_sync(0xffu, s, o);
        if (threadIdx.x == 0) atomicAdd(out, s);
    }
}

extern "C" void kernel_launch(void* const* d_in, const int* in_sizes, int n_in,
                              void* d_out, int out_size)
{
    const float* input  = (const float*)d_in[0];   // [B, N, 3]
    const float* target = (const float*)d_in[1];   // [B, M, 3]
    float* out = (float*)d_out;

    const int B = BATCH, D = 3;
    const int N = in_sizes[0] / (B * D);
    const int M = in_sizes[1] / (B * D);
    const int total = B * (N + M);

    init_kernel<<<(total + BLOCK - 1) / BLOCK, BLOCK>>>(out, total);

    const int g1 = (N + PTS_PER_BLOCK - 1) / PTS_PER_BLOCK;
    const int g2 = (M + PTS_PER_BLOCK - 1) / PTS_PER_BLOCK;
    dim3 grid(B * (g1 > g2 ? g1 : g2), MSPLIT, 2);
    chamfer_main<<<grid, BLOCK>>>(input, target, N, M);

    finalize_kernel<<<(total + BLOCK - 1) / BLOCK, BLOCK>>>(
        out, B * N, total,
        1.0f / ((float)B * (float)N), 1.0f / ((float)B * (float)M));
}